// round 3
// baseline (speedup 1.0000x reference)
#include <cuda_runtime.h>
#include <cuda_bf16.h>
#include <cstdint>

// Problem constants (fixed-shape benchmark)
#define B 8
#define C 256
#define H 128
#define W 128
#define HW (H * W)
#define CO 21
#define NSEG (B * CO)
#define EPS 1e-12f

#define N_FEAT (B * C * H * W)      // 33554432
#define N_OUT  (B * CO * H * W)     // 2752512
#define N_LAB  (B * H * W)          // 131072

// ---------------- scratch (device globals; no allocation) ----------------
__device__ unsigned char g_seg[B * HW];            // per-pixel class id (0..20)
__device__ float g_cnt[NSEG];                      // per-segment pixel count
__device__ float g_sum_cur[NSEG * C];              // segment sums (features)
__device__ float g_sum_ref[NSEG * C];              // segment sums (features_old)
__device__ float g_pc[NSEG * C];                   // normalized prototypes (cur)
__device__ float g_pr[NSEG * C];                   // normalized prototypes (ref)
__device__ float g_valid[NSEG];                    // 1.0 if segment counted in loss
__device__ float g_k;                              // number of valid prototypes
__device__ float g_sq;                             // sum of squared gram diffs (masked)

// ---------------- kernel 0: zero the accumulators ----------------
__global__ void k_zero() {
    int t = threadIdx.x;
    if (t < NSEG) g_cnt[t] = 0.0f;
    if (t == 0) { g_k = 0.0f; g_sq = 0.0f; }
}

// ---------------- kernel 1: pseudo labels + per-segment counts ----------------
// grid: (HW/256, B), block: 256
__global__ void k_pseudo(const float* __restrict__ outputs_old,
                         const int* __restrict__ labels,
                         const int* __restrict__ num_old_ptr) {
    int b = blockIdx.y;
    int p = blockIdx.x * 256 + threadIdx.x;
    int nold = *num_old_ptr;

    const float* oo = outputs_old + (size_t)b * CO * HW + p;
    float best = oo[0];
    int bi = 0;
#pragma unroll
    for (int c = 1; c < CO; ++c) {
        float v = __ldg(oo + (size_t)c * HW);
        if (v > best) { best = v; bi = c; }
    }
    int lab = labels[b * HW + p];
    int cls = (lab < nold) ? bi : 0;
    g_seg[b * HW + p] = (unsigned char)cls;

    __shared__ int hist[CO];
    if (threadIdx.x < CO) hist[threadIdx.x] = 0;
    __syncthreads();
    atomicAdd(&hist[cls], 1);
    __syncthreads();
    if (threadIdx.x < CO) {
        int hv = hist[threadIdx.x];
        if (hv) atomicAdd(&g_cnt[b * CO + threadIdx.x], (float)hv);
    }
}

// ---------------- kernel 2: segment sums (the HBM-bound kernel) ----------------
// grid: (C, B), block: 256. One block owns one (b,c) plane -> plain stores.
// Shared accumulators laid out [class][thread]: bank = tid%32, conflict-free.
__global__ __launch_bounds__(256) void k_segsum(const float* __restrict__ features,
                                                const float* __restrict__ features_old) {
    __shared__ float acc_cur[CO * 256];
    __shared__ float acc_ref[CO * 256];
    int tid = threadIdx.x;
    int c = blockIdx.x;
    int b = blockIdx.y;

#pragma unroll
    for (int s = 0; s < CO; ++s) {
        acc_cur[s * 256 + tid] = 0.0f;
        acc_ref[s * 256 + tid] = 0.0f;
    }
    __syncthreads();

    const float4* __restrict__ fc = (const float4*)(features     + ((size_t)b * C + c) * HW);
    const float4* __restrict__ fr = (const float4*)(features_old + ((size_t)b * C + c) * HW);
    const uchar4* __restrict__ sg = (const uchar4*)(g_seg + (size_t)b * HW);

    // 4096 float4 per plane; 16 iterations of 256 threads, unroll 8 for deep MLP
#pragma unroll 8
    for (int it = 0; it < 16; ++it) {
        int idx = it * 256 + tid;          // float4 index, 0..4095
        float4 xc = __ldg(fc + idx);
        float4 xr = __ldg(fr + idx);
        uchar4 s4 = sg[idx];
        acc_cur[(int)s4.x * 256 + tid] += xc.x;
        acc_cur[(int)s4.y * 256 + tid] += xc.y;
        acc_cur[(int)s4.z * 256 + tid] += xc.z;
        acc_cur[(int)s4.w * 256 + tid] += xc.w;
        acc_ref[(int)s4.x * 256 + tid] += xr.x;
        acc_ref[(int)s4.y * 256 + tid] += xr.y;
        acc_ref[(int)s4.z * 256 + tid] += xr.z;
        acc_ref[(int)s4.w * 256 + tid] += xr.w;
    }
    __syncthreads();

    int w = tid >> 5, l = tid & 31;
    for (int s = w; s < CO; s += 8) {
        float vc = 0.0f, vr = 0.0f;
#pragma unroll
        for (int q = l; q < 256; q += 32) {
            vc += acc_cur[s * 256 + q];
            vr += acc_ref[s * 256 + q];
        }
#pragma unroll
        for (int o = 16; o; o >>= 1) {
            vc += __shfl_down_sync(0xFFFFFFFFu, vc, o);
            vr += __shfl_down_sync(0xFFFFFFFFu, vr, o);
        }
        if (l == 0) {
            g_sum_cur[(b * CO + s) * C + c] = vc;
            g_sum_ref[(b * CO + s) * C + c] = vr;
        }
    }
}

// ---------------- kernel 3: normalize prototypes + validity ----------------
// grid: NSEG, block: 256 (one thread per channel)
__global__ void k_norm() {
    int i = blockIdx.x;
    int tid = threadIdx.x;
    float cnt = g_cnt[i];
    float denom = fmaxf(cnt, 1.0f);
    float vc = g_sum_cur[i * C + tid] / denom;
    float vr = g_sum_ref[i * C + tid] / denom;

    // block-reduce sum of squares for both
    __shared__ float rc[8], rr[8];
    float sc = vc * vc, sr = vr * vr;
#pragma unroll
    for (int o = 16; o; o >>= 1) {
        sc += __shfl_down_sync(0xFFFFFFFFu, sc, o);
        sr += __shfl_down_sync(0xFFFFFFFFu, sr, o);
    }
    int w = tid >> 5, l = tid & 31;
    if (l == 0) { rc[w] = sc; rr[w] = sr; }
    __syncthreads();
    float ssc = 0.0f, ssr = 0.0f;
#pragma unroll
    for (int q = 0; q < 8; ++q) { ssc += rc[q]; ssr += rr[q]; }

    float nc = fmaxf(sqrtf(ssc), EPS);
    float nr = fmaxf(sqrtf(ssr), EPS);
    g_pc[i * C + tid] = vc / nc;
    g_pr[i * C + tid] = vr / nr;

    if (tid == 0) {
        bool valid = (cnt > 0.0f) && ((i % CO) != 0);
        g_valid[i] = valid ? 1.0f : 0.0f;
        if (valid) atomicAdd(&g_k, 1.0f);
    }
}

// ---------------- kernel 4: masked Gram-difference MSE numerator ----------------
// grid: NSEG, block: 256. Row i kept in registers, j-rows streamed from L2.
__global__ void k_loss() {
    int i = blockIdx.x;
    if (g_valid[i] == 0.0f) return;
    int tid = threadIdx.x;
    __shared__ float spc[256], spr[256];
    spc[tid] = g_pc[i * C + tid];
    spr[tid] = g_pr[i * C + tid];
    __syncthreads();

    int w = tid >> 5, l = tid & 31;
    float ac[8], ar[8];
#pragma unroll
    for (int q = 0; q < 8; ++q) {
        ac[q] = spc[l + 32 * q];
        ar[q] = spr[l + 32 * q];
    }

    float part = 0.0f;
    for (int j = w; j < NSEG; j += 8) {
        if (g_valid[j] == 0.0f) continue;
        const float* qc = g_pc + j * C;
        const float* qr = g_pr + j * C;
        float dc = 0.0f, dr = 0.0f;
#pragma unroll
        for (int q = 0; q < 8; ++q) {
            dc += ac[q] * qc[l + 32 * q];
            dr += ar[q] * qr[l + 32 * q];
        }
#pragma unroll
        for (int o = 16; o; o >>= 1) {
            dc += __shfl_down_sync(0xFFFFFFFFu, dc, o);
            dr += __shfl_down_sync(0xFFFFFFFFu, dr, o);
        }
        if (l == 0) {
            float d = dc - dr;
            part += d * d;
        }
    }
    if (l == 0) atomicAdd(&g_sq, part);
}

// ---------------- kernel 5: finalize ----------------
__global__ void k_final(float* __restrict__ out) {
    float k = g_k;
    float sq = g_sq;
    out[0] = (k > 0.0f) ? (sq / fmaxf(k * k, 1.0f)) : 0.0f;
}

// ---------------- launch ----------------
extern "C" void kernel_launch(void* const* d_in, const int* in_sizes, int n_in,
                              void* d_out, int out_size) {
    // Resolve inputs by element count (robust to metadata ordering).
    // features/features_old: N_FEAT (loss is symmetric in the two, order moot)
    // outputs_old: N_OUT; labels: N_LAB (int32); num_old_class: 1; prototypes: CO*C.
    const float* features     = nullptr;
    const float* features_old = nullptr;
    const float* outputs_old  = nullptr;
    const int*   labels       = nullptr;
    const int*   num_old      = nullptr;
    for (int i = 0; i < n_in; ++i) {
        int sz = in_sizes[i];
        if (sz == N_FEAT) {
            if (!features) features = (const float*)d_in[i];
            else           features_old = (const float*)d_in[i];
        } else if (sz == N_OUT) {
            outputs_old = (const float*)d_in[i];
        } else if (sz == N_LAB) {
            labels = (const int*)d_in[i];
        } else if (sz == 1) {
            num_old = (const int*)d_in[i];
        }
        // CO*C prototypes: unused by the forward pass
    }
    float* out = (float*)d_out;

    k_zero<<<1, 256>>>();
    k_pseudo<<<dim3(HW / 256, B), 256>>>(outputs_old, labels, num_old);
    k_segsum<<<dim3(C, B), 256>>>(features, features_old);
    k_norm<<<NSEG, 256>>>();
    k_loss<<<NSEG, 256>>>();
    k_final<<<1, 1>>>(out);
}